// round 1
// baseline (speedup 1.0000x reference)
#include <cuda_runtime.h>

#define T_LEN 65536
#define H     128
#define G3    384   // 3*H gate rows

// Scratch: per-timestep hidden states for both directions (32 MB each).
__device__ float g_hf[T_LEN * H];
__device__ float g_hb[T_LEN * H];

__device__ __forceinline__ float sigmoid_fast(float x) {
    return 1.0f / (1.0f + __expf(-x));
}
__device__ __forceinline__ float tanh_fast(float x) {
    // tanh via exp of negative magnitude (no inf/inf NaN for large |x|)
    float ax = fabsf(x);
    float e  = __expf(-2.0f * ax);
    float t  = (1.0f - e) / (1.0f + e);
    return copysignf(t, x);
}

// Packed f32x2 FMA (2 MACs/instr) — only reachable via inline PTX on sm_103a.
__device__ __forceinline__ unsigned long long fma2(unsigned long long a,
                                                   unsigned long long b,
                                                   unsigned long long c) {
    unsigned long long d;
    asm("fma.rn.f32x2 %0, %1, %2, %3;" : "=l"(d) : "l"(a), "l"(b), "l"(c));
    return d;
}

// ---------------------------------------------------------------------------
// GRU kernel: grid = 2 blocks (block 0 = forward, block 1 = backward),
// 384 threads. Thread `tid` owns gate-row `tid` of Whh in registers
// (128 fp32 = 64 packed f32x2 regs). gate = tid>>7 (0=r, 1=z, 2=n), i = tid&127.
// ---------------------------------------------------------------------------
__global__ void __launch_bounds__(G3, 1) gru_kernel(
    const float* __restrict__ signal,
    const float* __restrict__ Wih_f, const float* __restrict__ Whh_f,
    const float* __restrict__ bih_f, const float* __restrict__ bhh_f,
    const float* __restrict__ Wih_b, const float* __restrict__ Whh_b,
    const float* __restrict__ bih_b, const float* __restrict__ bhh_b)
{
    const int dir = blockIdx.x;
    const float* __restrict__ Wih = dir ? Wih_b : Wih_f;
    const float* __restrict__ Whh = dir ? Whh_b : Whh_f;
    const float* __restrict__ bih = dir ? bih_b : bih_f;
    const float* __restrict__ bhh = dir ? bhh_b : bhh_f;
    float* __restrict__ hout = dir ? g_hb : g_hf;

    const int tid  = threadIdx.x;
    const int gate = tid >> 7;
    const int i    = tid & 127;

    __shared__ __align__(16) float h_sh[H];
    __shared__ float r_sh[H];
    __shared__ float z_sh[H];
    __shared__ float sig_sh[2048];

    // Register-resident recurrent weights: one full row per thread.
    unsigned long long w[64];
    {
        const unsigned long long* wrow =
            reinterpret_cast<const unsigned long long*>(Whh + tid * H);
        #pragma unroll
        for (int k = 0; k < 64; k++) w[k] = wrow[k];
    }
    const float wih  = Wih[tid];   // input dim is 1
    const float bihv = bih[tid];
    const float bhhv = bhh[tid];

    if (tid < H) h_sh[tid] = 0.0f;
    __syncthreads();

    for (int t = 0; t < T_LEN; t++) {
        const int off = t & 2047;
        if (off == 0) {
            __syncthreads();
            #pragma unroll
            for (int k = tid; k < 2048; k += G3) {
                const int idx = t + k;
                sig_sh[k] = dir ? signal[T_LEN - 1 - idx] : signal[idx];
            }
            __syncthreads();
        }

        const float x  = sig_sh[off];
        const float gi = fmaf(x, wih, bihv);

        // dot = Whh[row] . h   (packed f32x2, LDS.128 broadcast reads of h)
        const ulonglong2* h4 = reinterpret_cast<const ulonglong2*>(h_sh);
        unsigned long long a0 = 0ULL, a1 = 0ULL, a2 = 0ULL, a3 = 0ULL;
        #pragma unroll
        for (int q = 0; q < 32; q += 2) {
            ulonglong2 hv0 = h4[q];
            ulonglong2 hv1 = h4[q + 1];
            a0 = fma2(w[2 * q],     hv0.x, a0);
            a1 = fma2(w[2 * q + 1], hv0.y, a1);
            a2 = fma2(w[2 * q + 2], hv1.x, a2);
            a3 = fma2(w[2 * q + 3], hv1.y, a3);
        }
        float2 f0 = *reinterpret_cast<float2*>(&a0);
        float2 f1 = *reinterpret_cast<float2*>(&a1);
        float2 f2 = *reinterpret_cast<float2*>(&a2);
        float2 f3 = *reinterpret_cast<float2*>(&a3);
        const float dot = ((f0.x + f0.y) + (f1.x + f1.y)) +
                          ((f2.x + f2.y) + (f3.x + f3.y));
        const float hpre = dot + bhhv;           // gh row value

        if (gate == 0)      r_sh[i] = sigmoid_fast(gi + hpre);
        else if (gate == 1) z_sh[i] = sigmoid_fast(gi + hpre);
        __syncthreads();                          // r,z ready; h reads complete

        if (gate == 2) {
            const float n    = tanh_fast(gi + r_sh[i] * hpre);
            const float z    = z_sh[i];
            const float hold = h_sh[i];
            const float hnew = fmaf(z, hold - n, n);   // (1-z)*n + z*h
            h_sh[i] = hnew;
            const int tt = dir ? (T_LEN - 1 - t) : t;
            hout[tt * H + i] = hnew;
        }
        __syncthreads();                          // h_new visible
    }
}

// ---------------------------------------------------------------------------
// probs kernel: one warp per timestep. probs -> out[0:T], kept zeroed.
// ---------------------------------------------------------------------------
__global__ void probs_kernel(const float* __restrict__ w_out,
                             const float* __restrict__ b_out,
                             float* __restrict__ out)
{
    const int warp = threadIdx.x >> 5;
    const int lane = threadIdx.x & 31;
    const int t = blockIdx.x * 8 + warp;
    if (t >= T_LEN) return;

    const float* __restrict__ hf = g_hf + t * H;
    const float* __restrict__ hb = g_hb + t * H;
    float s = 0.0f;
    #pragma unroll
    for (int m = 0; m < 4; m++) {
        const int c = lane + 32 * m;
        s = fmaf(hf[c], w_out[c], s);
        s = fmaf(hb[c], w_out[H + c], s);
    }
    #pragma unroll
    for (int o = 16; o > 0; o >>= 1)
        s += __shfl_down_sync(0xffffffffu, s, o);
    if (lane == 0) {
        const float p = 1.0f / (1.0f + __expf(-(s + b_out[0])));
        out[t]         = p;
        out[T_LEN + t] = 0.0f;   // init kept
    }
}

// ---------------------------------------------------------------------------
// NMS: single block; threads prefetch prob chunks to shared (double buffer),
// thread 0 runs the sequential state machine.
// ---------------------------------------------------------------------------
#define NMS_CHUNK 4096
__global__ void nms_kernel(const float* __restrict__ probs,
                           float* __restrict__ kept)
{
    __shared__ float buf[2][NMS_CHUNK];
    const int tid = threadIdx.x;
    const int nchunks = T_LEN / NMS_CHUNK;

    // preload chunk 0
    for (int k = tid; k < NMS_CHUNK; k += blockDim.x) buf[0][k] = probs[k];

    int   win_end   = -1;
    int   best_idx  = 0;
    float best_prob = -1e30f;
    bool  have      = false;

    for (int c = 0; c < nchunks; c++) {
        __syncthreads();   // chunk c loaded, chunk (c+1)&1 free
        if (c + 1 < nchunks) {
            const int base = (c + 1) * NMS_CHUNK;
            for (int k = tid; k < NMS_CHUNK; k += blockDim.x)
                buf[(c + 1) & 1][k] = probs[base + k];
        }
        if (tid == 0) {
            const float4* b4 = reinterpret_cast<const float4*>(buf[c & 1]);
            const int tbase = c * NMS_CHUNK;
            for (int j = 0; j < NMS_CHUNK / 4; j++) {
                const float4 v = b4[j];
                float pv0 = v.x, pv1 = v.y, pv2 = v.z, pv3 = v.w;
                #pragma unroll
                for (int e = 0; e < 4; e++) {
                    const float p = (e == 0) ? pv0 : (e == 1) ? pv1
                                    : (e == 2) ? pv2 : pv3;
                    const int tt = tbase + 4 * j + e;
                    const bool is_peak = p > 0.5f;
                    const bool new_win = is_peak && (tt >= win_end);
                    if (new_win && have) kept[best_idx] = 1.0f;  // emit old best
                    if (new_win) win_end = tt + 40;              // MIN_DISTANCE
                    const bool take = new_win ||
                        (is_peak && !new_win && (p > best_prob));
                    if (take) { best_idx = tt; best_prob = p; }
                    have = have || is_peak;
                }
            }
        }
    }
    if (tid == 0 && have) kept[best_idx] = 1.0f;
}

// ---------------------------------------------------------------------------
extern "C" void kernel_launch(void* const* d_in, const int* in_sizes, int n_in,
                              void* d_out, int out_size)
{
    const float* signal = (const float*)d_in[0];
    const float* Wih_f  = (const float*)d_in[1];
    const float* Whh_f  = (const float*)d_in[2];
    const float* bih_f  = (const float*)d_in[3];
    const float* bhh_f  = (const float*)d_in[4];
    const float* Wih_b  = (const float*)d_in[5];
    const float* Whh_b  = (const float*)d_in[6];
    const float* bih_b  = (const float*)d_in[7];
    const float* bhh_b  = (const float*)d_in[8];
    const float* w_out  = (const float*)d_in[9];
    const float* b_out  = (const float*)d_in[10];
    float* out = (float*)d_out;

    gru_kernel<<<2, G3>>>(signal, Wih_f, Whh_f, bih_f, bhh_f,
                          Wih_b, Whh_b, bih_b, bhh_b);
    probs_kernel<<<T_LEN / 8, 256>>>(w_out, b_out, out);
    nms_kernel<<<1, 1024>>>(out, out + T_LEN);
}

// round 2
// speedup vs baseline: 1.1066x; 1.1066x over previous
#include <cuda_runtime.h>

#define T_LEN 65536
#define H     128

// Scratch: per-timestep hidden states for both directions.
__device__ float g_hf[T_LEN * H];
__device__ float g_hb[T_LEN * H];
__device__ unsigned g_maskw[T_LEN / 32];

__device__ __forceinline__ float sigmoid_fast(float x) {
    return 1.0f / (1.0f + __expf(-x));
}
__device__ __forceinline__ float tanh_fast(float x) {
    float ax = fabsf(x);
    float e  = __expf(-2.0f * ax);
    float t  = (1.0f - e) / (1.0f + e);
    return copysignf(t, x);
}

// Packed f32x2 FMA (2 MACs/instr) — only reachable via inline PTX on sm_103a.
__device__ __forceinline__ unsigned long long fma2(unsigned long long a,
                                                   unsigned long long b,
                                                   unsigned long long c) {
    unsigned long long d;
    asm("fma.rn.f32x2 %0, %1, %2, %3;" : "=l"(d) : "l"(a), "l"(b), "l"(c));
    return d;
}
__device__ __forceinline__ float hsum2(unsigned long long a, unsigned long long b) {
    unsigned long long s;
    asm("add.rn.f32x2 %0, %1, %2;" : "=l"(s) : "l"(a), "l"(b));
    float2 f = *reinterpret_cast<float2*>(&s);
    return f.x + f.y;
}

// ---------------------------------------------------------------------------
// GRU kernel: grid = 2 (dir), 256 threads = 128 unit-pairs.
// Thread (unit, half) owns the `half` 64-column slice of ALL THREE gate rows
// (r,z,n) of `unit` in registers (96 u64 = 192 regs of weights).
// Gates combine register-locally after one shfl_xor per gate.
// ONE __syncthreads per step; h double-buffered in shared.
// ---------------------------------------------------------------------------
__global__ void __launch_bounds__(256, 1) gru_kernel(
    const float* __restrict__ signal,
    const float* __restrict__ Wih_f, const float* __restrict__ Whh_f,
    const float* __restrict__ bih_f, const float* __restrict__ bhh_f,
    const float* __restrict__ Wih_b, const float* __restrict__ Whh_b,
    const float* __restrict__ bih_b, const float* __restrict__ bhh_b)
{
    const int dir = blockIdx.x;
    const float* __restrict__ Wih = dir ? Wih_b : Wih_f;
    const float* __restrict__ Whh = dir ? Whh_b : Whh_f;
    const float* __restrict__ bih = dir ? bih_b : bih_f;
    const float* __restrict__ bhh = dir ? bhh_b : bhh_f;
    float* __restrict__ hout = dir ? g_hb : g_hf;

    const int tid  = threadIdx.x;
    const int unit = tid >> 1;   // 0..127
    const int half = tid & 1;    // 0..1
    const int col0 = half << 6;  // 0 or 64

    __shared__ __align__(16) float h_sh[2][H];
    __shared__ float sig_sh[2048];

    const int row_r = unit;
    const int row_z = H + unit;
    const int row_n = 2 * H + unit;

    // Register-resident recurrent weights: 3 half-rows per thread.
    unsigned long long wr[32], wz[32], wn[32];
    {
        const unsigned long long* pr =
            reinterpret_cast<const unsigned long long*>(Whh + row_r * H + col0);
        const unsigned long long* pz =
            reinterpret_cast<const unsigned long long*>(Whh + row_z * H + col0);
        const unsigned long long* pn =
            reinterpret_cast<const unsigned long long*>(Whh + row_n * H + col0);
        #pragma unroll
        for (int k = 0; k < 32; k++) { wr[k] = pr[k]; wz[k] = pz[k]; wn[k] = pn[k]; }
    }
    const float wih_r = Wih[row_r], wih_z = Wih[row_z], wih_n = Wih[row_n];
    const float bih_r = bih[row_r], bih_z = bih[row_z], bih_n = bih[row_n];
    const float bhh_r = bhh[row_r], bhh_z = bhh[row_z], bhh_n = bhh[row_n];

    float hcur = 0.0f;
    if (tid < H) h_sh[0][tid] = 0.0f;
    __syncthreads();

    for (int t = 0; t < T_LEN; t++) {
        if ((t & 2047) == 0) {
            // previous step ended with __syncthreads -> safe to refill
            for (int k = tid; k < 2048; k += 256) {
                const int idx = t + k;
                sig_sh[k] = dir ? signal[T_LEN - 1 - idx] : signal[idx];
            }
            __syncthreads();
        }

        const float x = sig_sh[t & 2047];

        const ulonglong2* h4 =
            reinterpret_cast<const ulonglong2*>(&h_sh[t & 1][col0]);
        unsigned long long ar0 = 0ULL, ar1 = 0ULL;
        unsigned long long az0 = 0ULL, az1 = 0ULL;
        unsigned long long an0 = 0ULL, an1 = 0ULL;
        #pragma unroll
        for (int c = 0; c < 16; c++) {
            const ulonglong2 hv = h4[c];
            ar0 = fma2(wr[2 * c],     hv.x, ar0);
            ar1 = fma2(wr[2 * c + 1], hv.y, ar1);
            az0 = fma2(wz[2 * c],     hv.x, az0);
            az1 = fma2(wz[2 * c + 1], hv.y, az1);
            an0 = fma2(wn[2 * c],     hv.x, an0);
            an1 = fma2(wn[2 * c + 1], hv.y, an1);
        }
        float dr = hsum2(ar0, ar1);
        float dz = hsum2(az0, az1);
        float dn = hsum2(an0, an1);
        // pair-combine halves (lane ^ 1)
        dr += __shfl_xor_sync(0xffffffffu, dr, 1);
        dz += __shfl_xor_sync(0xffffffffu, dz, 1);
        dn += __shfl_xor_sync(0xffffffffu, dn, 1);

        const float r = sigmoid_fast(fmaf(x, wih_r, bih_r) + dr + bhh_r);
        const float z = sigmoid_fast(fmaf(x, wih_z, bih_z) + dz + bhh_z);
        const float n = tanh_fast(fmaf(x, wih_n, bih_n) + r * (dn + bhh_n));
        const float hnew = fmaf(z, hcur - n, n);   // (1-z)*n + z*h
        hcur = hnew;

        if (half == 0) {
            h_sh[(t + 1) & 1][unit] = hnew;
            const int tt = dir ? (T_LEN - 1 - t) : t;
            hout[tt * H + unit] = hnew;
        }
        __syncthreads();   // h_new visible; also fences WAR on h_sh read
    }
}

// ---------------------------------------------------------------------------
// probs kernel: one warp per timestep. probs -> out[0:T], kept zeroed.
// ---------------------------------------------------------------------------
__global__ void probs_kernel(const float* __restrict__ w_out,
                             const float* __restrict__ b_out,
                             float* __restrict__ out)
{
    const int warp = threadIdx.x >> 5;
    const int lane = threadIdx.x & 31;
    const int t = blockIdx.x * 8 + warp;
    if (t >= T_LEN) return;

    const float* __restrict__ hf = g_hf + t * H;
    const float* __restrict__ hb = g_hb + t * H;
    float s = 0.0f;
    #pragma unroll
    for (int m = 0; m < 4; m++) {
        const int c = lane + 32 * m;
        s = fmaf(hf[c], w_out[c], s);
        s = fmaf(hb[c], w_out[H + c], s);
    }
    #pragma unroll
    for (int o = 16; o > 0; o >>= 1)
        s += __shfl_down_sync(0xffffffffu, s, o);
    if (lane == 0) {
        const float p = 1.0f / (1.0f + __expf(-(s + b_out[0])));
        out[t]         = p;
        out[T_LEN + t] = 0.0f;   // init kept
    }
}

// ---------------------------------------------------------------------------
// mask kernel: probs > 0.5 bitmap via ballot.
// ---------------------------------------------------------------------------
__global__ void mask_kernel(const float* __restrict__ probs)
{
    const int t = blockIdx.x * blockDim.x + threadIdx.x;
    const unsigned b = __ballot_sync(0xffffffffu, probs[t] > 0.5f);
    if ((t & 31) == 0) g_maskw[t >> 5] = b;
}

// ---------------------------------------------------------------------------
// NMS: window starts via bitmap chase (thread 0, ~1.6k dependent steps),
// then warp-parallel argmax per window.
// Window semantics == reference scan: window [s, s+40); every window emits
// the earliest-max peak inside it.
// ---------------------------------------------------------------------------
__global__ void nms_kernel(const float* __restrict__ probs,
                           float* __restrict__ kept)
{
    __shared__ unsigned words[T_LEN / 32];
    __shared__ int starts[1700];
    __shared__ int nwin_sh;

    const int tid = threadIdx.x;
    for (int k = tid; k < T_LEN / 32; k += blockDim.x) words[k] = g_maskw[k];
    __syncthreads();

    if (tid == 0) {
        int nw = 0;
        int pos = 0;
        while (pos < T_LEN) {
            int wi = pos >> 5;
            unsigned w = words[wi] & (0xffffffffu << (pos & 31));
            while (w == 0) {
                wi++;
                if (wi >= T_LEN / 32) break;
                w = words[wi];
            }
            if (w == 0) break;
            const int s = (wi << 5) + __ffs(w) - 1;
            starts[nw++] = s;
            pos = s + 40;   // MIN_DISTANCE
        }
        nwin_sh = nw;
    }
    __syncthreads();

    const int nwin = nwin_sh;
    const int warp = tid >> 5;
    const int lane = tid & 31;
    for (int wdx = warp; wdx < nwin; wdx += 32) {
        const int s = starts[wdx];
        float bp = -1e30f;
        int   bi = 0x7fffffff;
        #pragma unroll
        for (int off = 0; off < 2; off++) {
            const int tt = s + lane + 32 * off;
            if (lane + 32 * off < 40 && tt < T_LEN) {
                const float p = probs[tt];
                if (p > 0.5f && (p > bp || (p == bp && tt < bi))) {
                    bp = p; bi = tt;
                }
            }
        }
        #pragma unroll
        for (int o = 16; o > 0; o >>= 1) {
            const float op = __shfl_xor_sync(0xffffffffu, bp, o);
            const int   oi = __shfl_xor_sync(0xffffffffu, bi, o);
            if (op > bp || (op == bp && oi < bi)) { bp = op; bi = oi; }
        }
        if (lane == 0) kept[bi] = 1.0f;
    }
}

// ---------------------------------------------------------------------------
extern "C" void kernel_launch(void* const* d_in, const int* in_sizes, int n_in,
                              void* d_out, int out_size)
{
    const float* signal = (const float*)d_in[0];
    const float* Wih_f  = (const float*)d_in[1];
    const float* Whh_f  = (const float*)d_in[2];
    const float* bih_f  = (const float*)d_in[3];
    const float* bhh_f  = (const float*)d_in[4];
    const float* Wih_b  = (const float*)d_in[5];
    const float* Whh_b  = (const float*)d_in[6];
    const float* bih_b  = (const float*)d_in[7];
    const float* bhh_b  = (const float*)d_in[8];
    const float* w_out  = (const float*)d_in[9];
    const float* b_out  = (const float*)d_in[10];
    float* out = (float*)d_out;

    gru_kernel<<<2, 256>>>(signal, Wih_f, Whh_f, bih_f, bhh_f,
                           Wih_b, Whh_b, bih_b, bhh_b);
    probs_kernel<<<T_LEN / 8, 256>>>(w_out, b_out, out);
    mask_kernel<<<T_LEN / 1024, 1024>>>(out);
    nms_kernel<<<1, 1024>>>(out, out + T_LEN);
}

// round 3
// speedup vs baseline: 1.1169x; 1.0093x over previous
#include <cuda_runtime.h>

#define T_LEN 65536
#define H     128

// Scratch: per-timestep hidden states for both directions.
__device__ float g_hf[T_LEN * H];
__device__ float g_hb[T_LEN * H];
__device__ unsigned g_maskw[T_LEN / 32];

// Fast approx math (MUFU only, no IEEE div sequences).
__device__ __forceinline__ float ex2a(float x) {
    float y; asm("ex2.approx.f32 %0, %1;" : "=f"(y) : "f"(x)); return y;
}
__device__ __forceinline__ float rcpa(float x) {
    float y; asm("rcp.approx.f32 %0, %1;" : "=f"(y) : "f"(x)); return y;
}
#define LOG2E 1.4426950408889634f
__device__ __forceinline__ float sigmoid_fast(float x) {
    return rcpa(1.0f + ex2a(-x * LOG2E));
}
__device__ __forceinline__ float tanh_fast(float x) {
    float ax = fabsf(x);
    float e  = ex2a(ax * (-2.0f * LOG2E));
    float t  = (1.0f - e) * rcpa(1.0f + e);
    return copysignf(t, x);
}

// Packed f32x2 FMA (2 MACs/instr) — only reachable via inline PTX on sm_103a.
__device__ __forceinline__ unsigned long long fma2(unsigned long long a,
                                                   unsigned long long b,
                                                   unsigned long long c) {
    unsigned long long d;
    asm("fma.rn.f32x2 %0, %1, %2, %3;" : "=l"(d) : "l"(a), "l"(b), "l"(c));
    return d;
}
__device__ __forceinline__ float hsum2(unsigned long long a, unsigned long long b) {
    unsigned long long s;
    asm("add.rn.f32x2 %0, %1, %2;" : "=l"(s) : "l"(a), "l"(b));
    float2 f = *reinterpret_cast<float2*>(&s);
    return f.x + f.y;
}

// ---------------------------------------------------------------------------
// GRU kernel: grid = 2 (dir), 512 threads = 128 units x 4 quarter-threads.
// Thread (unit, q) owns 32 columns of all three gate rows (r,z,n) of `unit`,
// in INTERLEAVED 16B granules: granule indices q, q+4, ..., q+28.
// -> each h LDS.128 reads contiguous 64B across q lanes (conflict-free,
//    8-lane broadcast), gate combine is a 2-level shfl_xor butterfly.
// 48 u64 weight regs/thread; ONE __syncthreads/step; ping-pong h buffer.
// ---------------------------------------------------------------------------
__global__ void __launch_bounds__(512, 1) gru_kernel(
    const float* __restrict__ signal,
    const float* __restrict__ Wih_f, const float* __restrict__ Whh_f,
    const float* __restrict__ bih_f, const float* __restrict__ bhh_f,
    const float* __restrict__ Wih_b, const float* __restrict__ Whh_b,
    const float* __restrict__ bih_b, const float* __restrict__ bhh_b)
{
    const int dir = blockIdx.x;
    const float* __restrict__ Wih = dir ? Wih_b : Wih_f;
    const float* __restrict__ Whh = dir ? Whh_b : Whh_f;
    const float* __restrict__ bih = dir ? bih_b : bih_f;
    const float* __restrict__ bhh = dir ? bhh_b : bhh_f;
    float* __restrict__ hout = dir ? g_hb : g_hf;

    const int tid  = threadIdx.x;
    const int unit = tid >> 2;   // 0..127
    const int q    = tid & 3;    // 0..3

    __shared__ __align__(16) float h_sh[2][H];
    __shared__ float sig_sh[4096];

    const int row_r = unit;
    const int row_z = H + unit;
    const int row_n = 2 * H + unit;

    // Register-resident weights: 8 granules (of 4 cols) per gate per thread.
    unsigned long long wr[16], wz[16], wn[16];
    #pragma unroll
    for (int k = 0; k < 8; k++) {
        const int g = q + 4 * k;       // granule index 0..31
        const unsigned long long* pr =
            reinterpret_cast<const unsigned long long*>(Whh + row_r * H + 4 * g);
        const unsigned long long* pz =
            reinterpret_cast<const unsigned long long*>(Whh + row_z * H + 4 * g);
        const unsigned long long* pn =
            reinterpret_cast<const unsigned long long*>(Whh + row_n * H + 4 * g);
        wr[2 * k] = pr[0]; wr[2 * k + 1] = pr[1];
        wz[2 * k] = pz[0]; wz[2 * k + 1] = pz[1];
        wn[2 * k] = pn[0]; wn[2 * k + 1] = pn[1];
    }
    const float wih_r = Wih[row_r], wih_z = Wih[row_z], wih_n = Wih[row_n];
    const float bih_r = bih[row_r], bih_z = bih[row_z], bih_n = bih[row_n];
    const float bhh_r = bhh[row_r], bhh_z = bhh[row_z], bhh_n = bhh[row_n];

    float hcur = 0.0f;
    if (tid < H) h_sh[0][tid] = 0.0f;
    __syncthreads();

    for (int t = 0; t < T_LEN; t++) {
        if ((t & 4095) == 0) {
            // previous step ended with __syncthreads -> safe to refill
            for (int k = tid; k < 4096; k += 512) {
                const int idx = t + k;
                sig_sh[k] = dir ? signal[T_LEN - 1 - idx] : signal[idx];
            }
            __syncthreads();
        }

        const float x = sig_sh[t & 4095];

        const ulonglong2* h4 =
            reinterpret_cast<const ulonglong2*>(h_sh[t & 1]);
        unsigned long long ar0 = 0ULL, ar1 = 0ULL;
        unsigned long long az0 = 0ULL, az1 = 0ULL;
        unsigned long long an0 = 0ULL, an1 = 0ULL;
        #pragma unroll
        for (int k = 0; k < 8; k++) {
            const ulonglong2 hv = h4[q + 4 * k];   // contiguous across q lanes
            ar0 = fma2(wr[2 * k],     hv.x, ar0);
            ar1 = fma2(wr[2 * k + 1], hv.y, ar1);
            az0 = fma2(wz[2 * k],     hv.x, az0);
            az1 = fma2(wz[2 * k + 1], hv.y, az1);
            an0 = fma2(wn[2 * k],     hv.x, an0);
            an1 = fma2(wn[2 * k + 1], hv.y, an1);
        }
        float dr = hsum2(ar0, ar1);
        float dz = hsum2(az0, az1);
        float dn = hsum2(an0, an1);
        // combine the 4 quarter-sums within the unit's lane group
        dr += __shfl_xor_sync(0xffffffffu, dr, 1);
        dz += __shfl_xor_sync(0xffffffffu, dz, 1);
        dn += __shfl_xor_sync(0xffffffffu, dn, 1);
        dr += __shfl_xor_sync(0xffffffffu, dr, 2);
        dz += __shfl_xor_sync(0xffffffffu, dz, 2);
        dn += __shfl_xor_sync(0xffffffffu, dn, 2);

        if (q == 0) {
            const float r = sigmoid_fast(fmaf(x, wih_r, bih_r) + dr + bhh_r);
            const float z = sigmoid_fast(fmaf(x, wih_z, bih_z) + dz + bhh_z);
            const float n = tanh_fast(fmaf(x, wih_n, bih_n) + r * (dn + bhh_n));
            const float hnew = fmaf(z, hcur - n, n);   // (1-z)*n + z*h
            hcur = hnew;
            h_sh[(t + 1) & 1][unit] = hnew;
            const int tt = dir ? (T_LEN - 1 - t) : t;
            hout[tt * H + unit] = hnew;
        }
        __syncthreads();   // h_new visible; also fences WAR on h_sh read
    }
}

// ---------------------------------------------------------------------------
// probs kernel: one warp per timestep. probs -> out[0:T], kept zeroed.
// ---------------------------------------------------------------------------
__global__ void probs_kernel(const float* __restrict__ w_out,
                             const float* __restrict__ b_out,
                             float* __restrict__ out)
{
    const int warp = threadIdx.x >> 5;
    const int lane = threadIdx.x & 31;
    const int t = blockIdx.x * 8 + warp;
    if (t >= T_LEN) return;

    const float* __restrict__ hf = g_hf + t * H;
    const float* __restrict__ hb = g_hb + t * H;
    float s = 0.0f;
    #pragma unroll
    for (int m = 0; m < 4; m++) {
        const int c = lane + 32 * m;
        s = fmaf(hf[c], w_out[c], s);
        s = fmaf(hb[c], w_out[H + c], s);
    }
    #pragma unroll
    for (int o = 16; o > 0; o >>= 1)
        s += __shfl_down_sync(0xffffffffu, s, o);
    if (lane == 0) {
        const float p = rcpa(1.0f + ex2a(-(s + b_out[0]) * LOG2E));
        out[t]         = p;
        out[T_LEN + t] = 0.0f;   // init kept
    }
}

// ---------------------------------------------------------------------------
// mask kernel: probs > 0.5 bitmap via ballot.
// ---------------------------------------------------------------------------
__global__ void mask_kernel(const float* __restrict__ probs)
{
    const int t = blockIdx.x * blockDim.x + threadIdx.x;
    const unsigned b = __ballot_sync(0xffffffffu, probs[t] > 0.5f);
    if ((t & 31) == 0) g_maskw[t >> 5] = b;
}

// ---------------------------------------------------------------------------
// NMS: window starts via bitmap chase (thread 0, ~1.6k dependent steps),
// then warp-parallel argmax per window.
// ---------------------------------------------------------------------------
__global__ void nms_kernel(const float* __restrict__ probs,
                           float* __restrict__ kept)
{
    __shared__ unsigned words[T_LEN / 32];
    __shared__ int starts[1700];
    __shared__ int nwin_sh;

    const int tid = threadIdx.x;
    for (int k = tid; k < T_LEN / 32; k += blockDim.x) words[k] = g_maskw[k];
    __syncthreads();

    if (tid == 0) {
        int nw = 0;
        int pos = 0;
        while (pos < T_LEN) {
            int wi = pos >> 5;
            unsigned w = words[wi] & (0xffffffffu << (pos & 31));
            while (w == 0) {
                wi++;
                if (wi >= T_LEN / 32) break;
                w = words[wi];
            }
            if (w == 0) break;
            const int s = (wi << 5) + __ffs(w) - 1;
            starts[nw++] = s;
            pos = s + 40;   // MIN_DISTANCE
        }
        nwin_sh = nw;
    }
    __syncthreads();

    const int nwin = nwin_sh;
    const int warp = tid >> 5;
    const int lane = tid & 31;
    for (int wdx = warp; wdx < nwin; wdx += 32) {
        const int s = starts[wdx];
        float bp = -1e30f;
        int   bi = 0x7fffffff;
        #pragma unroll
        for (int off = 0; off < 2; off++) {
            const int tt = s + lane + 32 * off;
            if (lane + 32 * off < 40 && tt < T_LEN) {
                const float p = probs[tt];
                if (p > 0.5f && (p > bp || (p == bp && tt < bi))) {
                    bp = p; bi = tt;
                }
            }
        }
        #pragma unroll
        for (int o = 16; o > 0; o >>= 1) {
            const float op = __shfl_xor_sync(0xffffffffu, bp, o);
            const int   oi = __shfl_xor_sync(0xffffffffu, bi, o);
            if (op > bp || (op == bp && oi < bi)) { bp = op; bi = oi; }
        }
        if (lane == 0) kept[bi] = 1.0f;
    }
}

// ---------------------------------------------------------------------------
extern "C" void kernel_launch(void* const* d_in, const int* in_sizes, int n_in,
                              void* d_out, int out_size)
{
    const float* signal = (const float*)d_in[0];
    const float* Wih_f  = (const float*)d_in[1];
    const float* Whh_f  = (const float*)d_in[2];
    const float* bih_f  = (const float*)d_in[3];
    const float* bhh_f  = (const float*)d_in[4];
    const float* Wih_b  = (const float*)d_in[5];
    const float* Whh_b  = (const float*)d_in[6];
    const float* bih_b  = (const float*)d_in[7];
    const float* bhh_b  = (const float*)d_in[8];
    const float* w_out  = (const float*)d_in[9];
    const float* b_out  = (const float*)d_in[10];
    float* out = (float*)d_out;

    gru_kernel<<<2, 512>>>(signal, Wih_f, Whh_f, bih_f, bhh_f,
                           Wih_b, Whh_b, bih_b, bhh_b);
    probs_kernel<<<T_LEN / 8, 256>>>(w_out, b_out, out);
    mask_kernel<<<T_LEN / 1024, 1024>>>(out);
    nms_kernel<<<1, 1024>>>(out, out + T_LEN);
}

// round 4
// speedup vs baseline: 1.2176x; 1.0901x over previous
#include <cuda_runtime.h>

#define T_LEN 65536
#define H     128

// Scratch: per-timestep hidden states for both directions.
__device__ float g_hf[T_LEN * H];
__device__ float g_hb[T_LEN * H];
__device__ unsigned g_maskw[T_LEN / 32];

// Fast approx math (MUFU only, no IEEE div sequences).
__device__ __forceinline__ float ex2a(float x) {
    float y; asm("ex2.approx.f32 %0, %1;" : "=f"(y) : "f"(x)); return y;
}
__device__ __forceinline__ float rcpa(float x) {
    float y; asm("rcp.approx.f32 %0, %1;" : "=f"(y) : "f"(x)); return y;
}
#define LOG2E 1.4426950408889634f
__device__ __forceinline__ float sigmoid_fast(float x) {
    return rcpa(1.0f + ex2a(-x * LOG2E));
}
__device__ __forceinline__ float tanh_fast(float x) {
    float ax = fabsf(x);
    float e  = ex2a(ax * (-2.0f * LOG2E));
    float t  = (1.0f - e) * rcpa(1.0f + e);
    return copysignf(t, x);
}

// Packed f32x2 FMA (2 MACs/instr) — only reachable via inline PTX on sm_103a.
__device__ __forceinline__ unsigned long long fma2(unsigned long long a,
                                                   unsigned long long b,
                                                   unsigned long long c) {
    unsigned long long d;
    asm("fma.rn.f32x2 %0, %1, %2, %3;" : "=l"(d) : "l"(a), "l"(b), "l"(c));
    return d;
}
__device__ __forceinline__ float hsum2(unsigned long long a, unsigned long long b) {
    unsigned long long s;
    asm("add.rn.f32x2 %0, %1, %2;" : "=l"(s) : "l"(a), "l"(b));
    float2 f = *reinterpret_cast<float2*>(&s);
    return f.x + f.y;
}

// ---------------------------------------------------------------------------
// GRU kernel: grid = 2 (dir), 256 threads = 128 unit-pairs (R2 partition:
// thread (unit, half) owns 64-col slice of rows r,z,n of `unit`, 96 u64 regs).
// KEY CHANGE vs R2: no per-step STG. hnew goes to a shared ring
// (2 buffers x 32 steps x 128 floats); every 32 steps one thread flushes a
// buffer with cp.async.bulk (async proxy => NOT drained by bar.sync).
// ---------------------------------------------------------------------------
__global__ void __launch_bounds__(256, 1) gru_kernel(
    const float* __restrict__ signal,
    const float* __restrict__ Wih_f, const float* __restrict__ Whh_f,
    const float* __restrict__ bih_f, const float* __restrict__ bhh_f,
    const float* __restrict__ Wih_b, const float* __restrict__ Whh_b,
    const float* __restrict__ bih_b, const float* __restrict__ bhh_b)
{
    const int dir = blockIdx.x;
    const float* __restrict__ Wih = dir ? Wih_b : Wih_f;
    const float* __restrict__ Whh = dir ? Whh_b : Whh_f;
    const float* __restrict__ bih = dir ? bih_b : bih_f;
    const float* __restrict__ bhh = dir ? bhh_b : bhh_f;
    float* __restrict__ hout = dir ? g_hb : g_hf;

    const int tid  = threadIdx.x;
    const int unit = tid >> 1;   // 0..127
    const int half = tid & 1;    // 0..1
    const int col0 = half << 6;  // 0 or 64

    __shared__ __align__(16) float h_sh[2][H];
    __shared__ __align__(16) float ring[2][32][H];   // 32 KB
    __shared__ float sig_sh[2048];                    // 8 KB

    const int row_r = unit;
    const int row_z = H + unit;
    const int row_n = 2 * H + unit;

    // Register-resident recurrent weights: 3 half-rows per thread.
    unsigned long long wr[32], wz[32], wn[32];
    {
        const unsigned long long* pr =
            reinterpret_cast<const unsigned long long*>(Whh + row_r * H + col0);
        const unsigned long long* pz =
            reinterpret_cast<const unsigned long long*>(Whh + row_z * H + col0);
        const unsigned long long* pn =
            reinterpret_cast<const unsigned long long*>(Whh + row_n * H + col0);
        #pragma unroll
        for (int k = 0; k < 32; k++) { wr[k] = pr[k]; wz[k] = pz[k]; wn[k] = pn[k]; }
    }
    const float wih_r = Wih[row_r], wih_z = Wih[row_z], wih_n = Wih[row_n];
    const float bih_r = bih[row_r], bih_z = bih[row_z], bih_n = bih[row_n];
    const float bhh_r = bhh[row_r], bhh_z = bhh[row_z], bhh_n = bhh[row_n];

    float hcur = 0.0f;
    if (tid < H) h_sh[0][tid] = 0.0f;
    __syncthreads();

    for (int t = 0; t < T_LEN; t++) {
        if ((t & 2047) == 0) {
            // previous step ended with __syncthreads -> safe to refill
            for (int k = tid; k < 2048; k += 256) {
                const int idx = t + k;
                sig_sh[k] = dir ? signal[T_LEN - 1 - idx] : signal[idx];
            }
            __syncthreads();
        }

        const float x = sig_sh[t & 2047];

        const ulonglong2* h4 =
            reinterpret_cast<const ulonglong2*>(&h_sh[t & 1][col0]);
        unsigned long long ar0 = 0ULL, ar1 = 0ULL;
        unsigned long long az0 = 0ULL, az1 = 0ULL;
        unsigned long long an0 = 0ULL, an1 = 0ULL;
        #pragma unroll
        for (int c = 0; c < 16; c++) {
            const ulonglong2 hv = h4[c];
            ar0 = fma2(wr[2 * c],     hv.x, ar0);
            ar1 = fma2(wr[2 * c + 1], hv.y, ar1);
            az0 = fma2(wz[2 * c],     hv.x, az0);
            az1 = fma2(wz[2 * c + 1], hv.y, az1);
            an0 = fma2(wn[2 * c],     hv.x, an0);
            an1 = fma2(wn[2 * c + 1], hv.y, an1);
        }
        float dr = hsum2(ar0, ar1);
        float dz = hsum2(az0, az1);
        float dn = hsum2(an0, an1);
        // pair-combine halves (lane ^ 1)
        dr += __shfl_xor_sync(0xffffffffu, dr, 1);
        dz += __shfl_xor_sync(0xffffffffu, dz, 1);
        dn += __shfl_xor_sync(0xffffffffu, dn, 1);

        const float r = sigmoid_fast(fmaf(x, wih_r, bih_r) + dr + bhh_r);
        const float z = sigmoid_fast(fmaf(x, wih_z, bih_z) + dz + bhh_z);
        const float n = tanh_fast(fmaf(x, wih_n, bih_n) + r * (dn + bhh_n));
        const float hnew = fmaf(z, hcur - n, n);   // (1-z)*n + z*h
        hcur = hnew;

        if (half == 0) {
            h_sh[(t + 1) & 1][unit] = hnew;
            // shared ring instead of STG: backward dir stores reversed so the
            // buffer is an ascending-contiguous global chunk.
            const int slot = dir ? (31 - (t & 31)) : (t & 31);
            ring[(t >> 5) & 1][slot][unit] = hnew;
        }
        __syncthreads();   // h_new + ring slot visible; fences WAR on h_sh

        if ((t & 31) == 31 && tid == 0) {
            const int buf = (t >> 5) & 1;
            float* dst = dir ? (hout + (T_LEN - 1 - t) * H)
                             : (hout + (t - 31) * H);
            unsigned s = (unsigned)__cvta_generic_to_shared(&ring[buf][0][0]);
            asm volatile("fence.proxy.async.shared::cta;" ::: "memory");
            asm volatile(
                "cp.async.bulk.global.shared::cta.bulk_group [%0], [%1], %2;"
                :: "l"(dst), "r"(s), "r"(32 * H * 4) : "memory");
            asm volatile("cp.async.bulk.commit_group;" ::: "memory");
            // previous buffer's copy must have finished READING before reuse
            asm volatile("cp.async.bulk.wait_group.read 1;" ::: "memory");
        }
    }

    // all bulk copies must complete before CTA exit
    if (tid == 0)
        asm volatile("cp.async.bulk.wait_group 0;" ::: "memory");
    __syncthreads();
}

// ---------------------------------------------------------------------------
// probs kernel: one warp per timestep. probs -> out[0:T], kept zeroed.
// ---------------------------------------------------------------------------
__global__ void probs_kernel(const float* __restrict__ w_out,
                             const float* __restrict__ b_out,
                             float* __restrict__ out)
{
    const int warp = threadIdx.x >> 5;
    const int lane = threadIdx.x & 31;
    const int t = blockIdx.x * 8 + warp;
    if (t >= T_LEN) return;

    const float* __restrict__ hf = g_hf + t * H;
    const float* __restrict__ hb = g_hb + t * H;
    float s = 0.0f;
    #pragma unroll
    for (int m = 0; m < 4; m++) {
        const int c = lane + 32 * m;
        s = fmaf(hf[c], w_out[c], s);
        s = fmaf(hb[c], w_out[H + c], s);
    }
    #pragma unroll
    for (int o = 16; o > 0; o >>= 1)
        s += __shfl_down_sync(0xffffffffu, s, o);
    if (lane == 0) {
        const float p = rcpa(1.0f + ex2a(-(s + b_out[0]) * LOG2E));
        out[t]         = p;
        out[T_LEN + t] = 0.0f;   // init kept
    }
}

// ---------------------------------------------------------------------------
// mask kernel: probs > 0.5 bitmap via ballot.
// ---------------------------------------------------------------------------
__global__ void mask_kernel(const float* __restrict__ probs)
{
    const int t = blockIdx.x * blockDim.x + threadIdx.x;
    const unsigned b = __ballot_sync(0xffffffffu, probs[t] > 0.5f);
    if ((t & 31) == 0) g_maskw[t >> 5] = b;
}

// ---------------------------------------------------------------------------
// NMS: window starts via bitmap chase (thread 0, ~1.6k dependent steps),
// then warp-parallel argmax per window.
// ---------------------------------------------------------------------------
__global__ void nms_kernel(const float* __restrict__ probs,
                           float* __restrict__ kept)
{
    __shared__ unsigned words[T_LEN / 32];
    __shared__ int starts[1700];
    __shared__ int nwin_sh;

    const int tid = threadIdx.x;
    for (int k = tid; k < T_LEN / 32; k += blockDim.x) words[k] = g_maskw[k];
    __syncthreads();

    if (tid == 0) {
        int nw = 0;
        int pos = 0;
        while (pos < T_LEN) {
            int wi = pos >> 5;
            unsigned w = words[wi] & (0xffffffffu << (pos & 31));
            while (w == 0) {
                wi++;
                if (wi >= T_LEN / 32) break;
                w = words[wi];
            }
            if (w == 0) break;
            const int s = (wi << 5) + __ffs(w) - 1;
            starts[nw++] = s;
            pos = s + 40;   // MIN_DISTANCE
        }
        nwin_sh = nw;
    }
    __syncthreads();

    const int nwin = nwin_sh;
    const int warp = tid >> 5;
    const int lane = tid & 31;
    for (int wdx = warp; wdx < nwin; wdx += 32) {
        const int s = starts[wdx];
        float bp = -1e30f;
        int   bi = 0x7fffffff;
        #pragma unroll
        for (int off = 0; off < 2; off++) {
            const int tt = s + lane + 32 * off;
            if (lane + 32 * off < 40 && tt < T_LEN) {
                const float p = probs[tt];
                if (p > 0.5f && (p > bp || (p == bp && tt < bi))) {
                    bp = p; bi = tt;
                }
            }
        }
        #pragma unroll
        for (int o = 16; o > 0; o >>= 1) {
            const float op = __shfl_xor_sync(0xffffffffu, bp, o);
            const int   oi = __shfl_xor_sync(0xffffffffu, bi, o);
            if (op > bp || (op == bp && oi < bi)) { bp = op; bi = oi; }
        }
        if (lane == 0) kept[bi] = 1.0f;
    }
}

// ---------------------------------------------------------------------------
extern "C" void kernel_launch(void* const* d_in, const int* in_sizes, int n_in,
                              void* d_out, int out_size)
{
    const float* signal = (const float*)d_in[0];
    const float* Wih_f  = (const float*)d_in[1];
    const float* Whh_f  = (const float*)d_in[2];
    const float* bih_f  = (const float*)d_in[3];
    const float* bhh_f  = (const float*)d_in[4];
    const float* Wih_b  = (const float*)d_in[5];
    const float* Whh_b  = (const float*)d_in[6];
    const float* bih_b  = (const float*)d_in[7];
    const float* bhh_b  = (const float*)d_in[8];
    const float* w_out  = (const float*)d_in[9];
    const float* b_out  = (const float*)d_in[10];
    float* out = (float*)d_out;

    gru_kernel<<<2, 256>>>(signal, Wih_f, Whh_f, bih_f, bhh_f,
                           Wih_b, Whh_b, bih_b, bhh_b);
    probs_kernel<<<T_LEN / 8, 256>>>(w_out, b_out, out);
    mask_kernel<<<T_LEN / 1024, 1024>>>(out);
    nms_kernel<<<1, 1024>>>(out, out + T_LEN);
}